// round 1
// baseline (speedup 1.0000x reference)
#include <cuda_runtime.h>
#include <math.h>

#define BB 2
#define NN 8192
#define KK 32
#define CC 128
#define HH 128
#define ALPHA 0.3f
#define EPS 1e-6f

// Scratch (device globals -- allocation inside kernel_launch is forbidden)
__device__ float g_H[(size_t)BB * NN * HH];    // leaky(emb @ Qw + Qb), 8 MB
__device__ float g_wsh[(size_t)BB * NN * HH];  // weighted-sum hidden,  8 MB

// ---------------------------------------------------------------------------
// K1: H_all[row, h] = leaky(sum_c emb[row,c] * Qw[c,h] + Qb[h])
// row = b*N + n, rows 0..16383. One block = 32 rows, 128 threads (1 per h).
// ---------------------------------------------------------------------------
__global__ void __launch_bounds__(128) k1_qgemm(const float* __restrict__ emb,
                                                const float* __restrict__ Qw,
                                                const float* __restrict__ Qb) {
    const int RB = 32;
    __shared__ float es[RB][CC];
    const int row0 = blockIdx.x * RB;
    const int t = threadIdx.x;

    // Cooperative load of 32 full rows (contiguous): 4096 floats = 1024 float4
    const float4* src = (const float4*)(emb + (size_t)row0 * CC);
    float4* dst = (float4*)&es[0][0];
#pragma unroll
    for (int i = 0; i < (RB * CC / 4) / 128; i++)
        dst[t + i * 128] = src[t + i * 128];
    __syncthreads();

    float acc[RB];
#pragma unroll
    for (int r = 0; r < RB; r++) acc[r] = 0.f;

#pragma unroll 4
    for (int c = 0; c < CC; c++) {
        float w = Qw[c * HH + t];   // coalesced, L1-resident (64 KB)
#pragma unroll
        for (int r = 0; r < RB; r++) acc[r] += es[r][c] * w;
    }

    const float b = Qb[t];
#pragma unroll
    for (int r = 0; r < RB; r++) {
        float v = acc[r] + b;
        v = (v >= 0.f) ? v : ALPHA * v;
        g_H[(size_t)(row0 + r) * HH + t] = v;
    }
}

// ---------------------------------------------------------------------------
// K2: wsh[b,n,h] = sum_k H[b, ns[n,k], h] * w[n, ns[n,k]] / (sum_k w + eps)
// One block per (n, b): consecutive blocks share n so the scattered weights
// lines are reused out of L2 by the second batch. 128 threads (1 per h).
// ---------------------------------------------------------------------------
__global__ void __launch_bounds__(128) k2_gather(const float* __restrict__ weights,
                                                 const int* __restrict__ ns) {
    const int bn = blockIdx.x;
    const int n = bn >> 1;
    const int b = bn & 1;
    const int t = threadIdx.x;

    __shared__ float ws[KK];
    __shared__ int   js[KK];
    __shared__ float wsum_s;

    if (t < KK) {  // warp 0 exactly
        int j = ns[n * KK + t];
        js[t] = j;
        float w = weights[(size_t)n * NN + j];
        ws[t] = w;
#pragma unroll
        for (int off = 16; off; off >>= 1)
            w += __shfl_xor_sync(0xffffffffu, w, off);
        if (t == 0) wsum_s = w;
    }
    __syncthreads();

    const float* Hb = g_H + (size_t)b * NN * HH;
    float acc = 0.f;
#pragma unroll
    for (int k = 0; k < KK; k++)
        acc += Hb[(size_t)js[k] * HH + t] * ws[k];   // 512B coalesced row, L2 hit

    g_wsh[((size_t)b * NN + n) * HH + t] = acc / (wsum_s + EPS);
}

// ---------------------------------------------------------------------------
// K3: out[row,h] = normalize_h( leaky( [emb_row | wsh_row] @ Ww + Wb ) )
// One block = 16 rows, 128 threads (1 per h). Fused leaky + L2-norm epilogue.
// ---------------------------------------------------------------------------
__global__ void __launch_bounds__(128) k3_out(const float* __restrict__ emb,
                                              const float* __restrict__ Ww,
                                              const float* __restrict__ Wb,
                                              float* __restrict__ out) {
    const int RB = 16;
    __shared__ float cs[RB][CC + HH];   // 16 KB
    __shared__ float red[RB][4];
    const int row0 = blockIdx.x * RB;
    const int t = threadIdx.x;

    // emb rows and wsh rows are each RB*128 contiguous floats = 512 float4
    const float4* se = (const float4*)(emb   + (size_t)row0 * CC);
    const float4* sw = (const float4*)(g_wsh + (size_t)row0 * HH);
#pragma unroll
    for (int i = 0; i < (RB * CC / 4) / 128; i++) {
        int idx = t + i * 128;
        int r = idx >> 5;          // idx / 32 float4s per row
        int c4 = idx & 31;
        ((float4*)&cs[r][0])[c4]  = se[idx];
        ((float4*)&cs[r][CC])[c4] = sw[idx];
    }
    __syncthreads();

    float acc[RB];
#pragma unroll
    for (int r = 0; r < RB; r++) acc[r] = 0.f;

#pragma unroll 4
    for (int f = 0; f < CC + HH; f++) {
        float w = Ww[f * HH + t];   // coalesced, 128 KB -> L1/L2-resident
#pragma unroll
        for (int r = 0; r < RB; r++) acc[r] += cs[r][f] * w;
    }

    const float b = Wb[t];
    const int warp = t >> 5, lane = t & 31;
#pragma unroll
    for (int r = 0; r < RB; r++) {
        float v = acc[r] + b;
        v = (v >= 0.f) ? v : ALPHA * v;
        acc[r] = v;
        float s = v * v;
#pragma unroll
        for (int off = 16; off; off >>= 1)
            s += __shfl_xor_sync(0xffffffffu, s, off);
        if (lane == 0) red[r][warp] = s;
    }
    __syncthreads();

#pragma unroll
    for (int r = 0; r < RB; r++) {
        float nrm = sqrtf(red[r][0] + red[r][1] + red[r][2] + red[r][3]);
        out[(size_t)(row0 + r) * HH + t] = acc[r] / (nrm + EPS);
    }
}

// ---------------------------------------------------------------------------
extern "C" void kernel_launch(void* const* d_in, const int* in_sizes, int n_in,
                              void* d_out, int out_size) {
    const float* emb     = (const float*)d_in[0];  // (B, N, C)
    const float* weights = (const float*)d_in[1];  // (N, N)
    const int*   ns      = (const int*)  d_in[2];  // (N, K)
    const float* Qw      = (const float*)d_in[3];  // (C, H)
    const float* Qb      = (const float*)d_in[4];  // (H,)
    const float* Ww      = (const float*)d_in[5];  // (C+H, H)
    const float* Wb      = (const float*)d_in[6];  // (H,)
    float* out = (float*)d_out;                    // (B, N, H)

    (void)in_sizes; (void)n_in; (void)out_size;

    k1_qgemm<<<(BB * NN) / 32, 128>>>(emb, Qw, Qb);
    k2_gather<<<BB * NN, 128>>>(weights, ns);
    k3_out<<<(BB * NN) / 16, 128>>>(emb, Ww, Wb, out);
}

// round 2
// speedup vs baseline: 1.4365x; 1.4365x over previous
#include <cuda_runtime.h>
#include <math.h>

#define BB 2
#define NN 8192
#define KK 32
#define CC 128
#define HH 128
#define ALPHA 0.3f
#define EPS 1e-6f

// Scratch (device globals -- allocation inside kernel_launch is forbidden)
__device__ float g_H[(size_t)BB * NN * HH];    // leaky(emb @ Qw + Qb), 8 MB
__device__ float g_wsh[(size_t)BB * NN * HH];  // weighted-sum hidden,  8 MB

// ---------------------------------------------------------------------------
// K1: H_all[row, h] = leaky(sum_c emb[row,c] * Qw[c,h] + Qb[h])
// One block = 32 rows, 128 threads (thread t owns output column h=t).
// Inner product vectorized: one LDS.128 feeds 4 FFMAs.
// ---------------------------------------------------------------------------
__global__ void __launch_bounds__(128) k1_qgemm(const float* __restrict__ emb,
                                                const float* __restrict__ Qw,
                                                const float* __restrict__ Qb) {
    const int RB = 32;
    __shared__ float es[RB][CC];
    const int row0 = blockIdx.x * RB;
    const int t = threadIdx.x;

    const float4* src = (const float4*)(emb + (size_t)row0 * CC);
    float4* dst = (float4*)&es[0][0];
#pragma unroll
    for (int i = 0; i < (RB * CC / 4) / 128; i++)
        dst[t + i * 128] = src[t + i * 128];
    __syncthreads();

    float acc[RB];
#pragma unroll
    for (int r = 0; r < RB; r++) acc[r] = 0.f;

#pragma unroll 2
    for (int c = 0; c < CC; c += 4) {
        const float w0 = Qw[(c + 0) * HH + t];
        const float w1 = Qw[(c + 1) * HH + t];
        const float w2 = Qw[(c + 2) * HH + t];
        const float w3 = Qw[(c + 3) * HH + t];
#pragma unroll
        for (int r = 0; r < RB; r++) {
            float4 e = *(const float4*)&es[r][c];   // LDS.128 broadcast
            acc[r] = fmaf(e.x, w0, acc[r]);
            acc[r] = fmaf(e.y, w1, acc[r]);
            acc[r] = fmaf(e.z, w2, acc[r]);
            acc[r] = fmaf(e.w, w3, acc[r]);
        }
    }

    const float b = Qb[t];
#pragma unroll
    for (int r = 0; r < RB; r++) {
        float v = acc[r] + b;
        v = (v >= 0.f) ? v : ALPHA * v;
        g_H[(size_t)(row0 + r) * HH + t] = v;
    }
}

// ---------------------------------------------------------------------------
// K2: wsh[b,n,h] = sum_k H[b, ns[n,k], h] * w[n, ns[n,k]] / (sum_k w + eps)
// One block per n computes BOTH batches (shares gathered weights + indices).
// ---------------------------------------------------------------------------
__global__ void __launch_bounds__(128) k2_gather(const float* __restrict__ weights,
                                                 const int* __restrict__ ns) {
    const int n = blockIdx.x;
    const int t = threadIdx.x;

    __shared__ float ws[KK];
    __shared__ int   js[KK];
    __shared__ float wsum_s;

    if (t < KK) {  // warp 0 exactly
        int j = ns[n * KK + t];
        js[t] = j;
        float w = weights[(size_t)n * NN + j];
        ws[t] = w;
#pragma unroll
        for (int off = 16; off; off >>= 1)
            w += __shfl_xor_sync(0xffffffffu, w, off);
        if (t == 0) wsum_s = w;
    }
    __syncthreads();

    const float* H0 = g_H;
    const float* H1 = g_H + (size_t)NN * HH;
    float acc0 = 0.f, acc1 = 0.f;
#pragma unroll
    for (int k = 0; k < KK; k++) {
        const int j = js[k];
        const float w = ws[k];
        acc0 = fmaf(H0[(size_t)j * HH + t], w, acc0);
        acc1 = fmaf(H1[(size_t)j * HH + t], w, acc1);
    }

    const float inv = 1.f / (wsum_s + EPS);
    g_wsh[(size_t)n * HH + t] = acc0 * inv;
    g_wsh[((size_t)NN + n) * HH + t] = acc1 * inv;
}

// ---------------------------------------------------------------------------
// K3: out[row,h] = normalize_h( leaky( [emb_row | wsh_row] @ Ww + Wb ) )
// One block = 16 rows, 128 threads. Vectorized LDS.128 inner loop,
// fused leaky + L2-norm epilogue.
// ---------------------------------------------------------------------------
__global__ void __launch_bounds__(128) k3_out(const float* __restrict__ emb,
                                              const float* __restrict__ Ww,
                                              const float* __restrict__ Wb,
                                              float* __restrict__ out) {
    const int RB = 16;
    __shared__ float cs[RB][CC + HH];   // 16 KB
    __shared__ float red[RB][4];
    const int row0 = blockIdx.x * RB;
    const int t = threadIdx.x;

    const float4* se = (const float4*)(emb   + (size_t)row0 * CC);
    const float4* sw = (const float4*)(g_wsh + (size_t)row0 * HH);
#pragma unroll
    for (int i = 0; i < (RB * CC / 4) / 128; i++) {
        int idx = t + i * 128;
        int r = idx >> 5;
        int c4 = idx & 31;
        ((float4*)&cs[r][0])[c4]  = se[idx];
        ((float4*)&cs[r][CC])[c4] = sw[idx];
    }
    __syncthreads();

    float acc[RB];
#pragma unroll
    for (int r = 0; r < RB; r++) acc[r] = 0.f;

#pragma unroll 2
    for (int f = 0; f < CC + HH; f += 4) {
        const float w0 = Ww[(f + 0) * HH + t];
        const float w1 = Ww[(f + 1) * HH + t];
        const float w2 = Ww[(f + 2) * HH + t];
        const float w3 = Ww[(f + 3) * HH + t];
#pragma unroll
        for (int r = 0; r < RB; r++) {
            float4 e = *(const float4*)&cs[r][f];   // LDS.128 broadcast
            acc[r] = fmaf(e.x, w0, acc[r]);
            acc[r] = fmaf(e.y, w1, acc[r]);
            acc[r] = fmaf(e.z, w2, acc[r]);
            acc[r] = fmaf(e.w, w3, acc[r]);
        }
    }

    const float b = Wb[t];
    const int warp = t >> 5, lane = t & 31;
#pragma unroll
    for (int r = 0; r < RB; r++) {
        float v = acc[r] + b;
        v = (v >= 0.f) ? v : ALPHA * v;
        acc[r] = v;
        float s = v * v;
#pragma unroll
        for (int off = 16; off; off >>= 1)
            s += __shfl_xor_sync(0xffffffffu, s, off);
        if (lane == 0) red[r][warp] = s;
    }
    __syncthreads();

#pragma unroll
    for (int r = 0; r < RB; r++) {
        float nrm = sqrtf(red[r][0] + red[r][1] + red[r][2] + red[r][3]);
        out[(size_t)(row0 + r) * HH + t] = acc[r] / (nrm + EPS);
    }
}

// ---------------------------------------------------------------------------
extern "C" void kernel_launch(void* const* d_in, const int* in_sizes, int n_in,
                              void* d_out, int out_size) {
    const float* emb     = (const float*)d_in[0];  // (B, N, C)
    const float* weights = (const float*)d_in[1];  // (N, N)
    const int*   ns      = (const int*)  d_in[2];  // (N, K)
    const float* Qw      = (const float*)d_in[3];  // (C, H)
    const float* Qb      = (const float*)d_in[4];  // (H,)
    const float* Ww      = (const float*)d_in[5];  // (C+H, H)
    const float* Wb      = (const float*)d_in[6];  // (H,)
    float* out = (float*)d_out;                    // (B, N, H)

    (void)in_sizes; (void)n_in; (void)out_size;

    k1_qgemm<<<(BB * NN) / 32, 128>>>(emb, Qw, Qb);
    k2_gather<<<NN, 128>>>(weights, ns);
    k3_out<<<(BB * NN) / 16, 128>>>(emb, Ww, Wb, out);
}

// round 3
// speedup vs baseline: 1.5011x; 1.0450x over previous
#include <cuda_runtime.h>
#include <math.h>

#define BB 2
#define NN 8192
#define KK 32
#define CC 128
#define HH 128
#define ALPHA 0.3f
#define EPS 1e-6f

__device__ float g_H[(size_t)BB * NN * HH];    // leaky(emb @ Qw + Qb), 8 MB
__device__ float g_wsh[(size_t)BB * NN * HH];  // weighted-sum hidden,  8 MB

// ---- packed fp32x2 helpers (Blackwell FFMA2; 2x fp32 throughput) ----------
__device__ __forceinline__ void ffma2(unsigned long long& acc,
                                      unsigned long long a,
                                      unsigned long long b) {
    asm("fma.rn.f32x2 %0, %1, %2, %0;" : "+l"(acc) : "l"(a), "l"(b));
}
__device__ __forceinline__ unsigned long long pack2(float lo, float hi) {
    unsigned long long r;
    asm("mov.b64 %0, {%1, %2};" : "=l"(r) : "f"(lo), "f"(hi));
    return r;
}
__device__ __forceinline__ float unpack_sum(unsigned long long v) {
    float lo, hi;
    asm("mov.b64 {%0, %1}, %2;" : "=f"(lo), "=f"(hi) : "l"(v));
    return lo + hi;
}

// ---------------------------------------------------------------------------
// K1: H[row,h] = leaky(sum_c emb[row,c]*Qw[c,h] + Qb[h])
// Block = 16 rows x 128 threads (thread t owns column h=t).
// acc2 lanes = (even-c partial, odd-c partial); one LDS.128 -> 2 FFMA2.
// ---------------------------------------------------------------------------
__global__ void __launch_bounds__(128) k1_qgemm(const float* __restrict__ emb,
                                                const float* __restrict__ Qw,
                                                const float* __restrict__ Qb) {
    const int RB = 16;
    __shared__ float es[RB][CC];
    const int row0 = blockIdx.x * RB;
    const int t = threadIdx.x;

    const float4* src = (const float4*)(emb + (size_t)row0 * CC);
    float4* dst = (float4*)&es[0][0];
#pragma unroll
    for (int i = 0; i < (RB * CC / 4) / 128; i++)
        dst[t + i * 128] = src[t + i * 128];
    __syncthreads();

    unsigned long long acc[RB];
#pragma unroll
    for (int r = 0; r < RB; r++) acc[r] = 0ull;

#pragma unroll 4
    for (int c = 0; c < CC; c += 4) {
        const unsigned long long w01 = pack2(Qw[(c + 0) * HH + t], Qw[(c + 1) * HH + t]);
        const unsigned long long w23 = pack2(Qw[(c + 2) * HH + t], Qw[(c + 3) * HH + t]);
#pragma unroll
        for (int r = 0; r < RB; r++) {
            const ulonglong2 e = *(const ulonglong2*)&es[r][c];  // LDS.128 -> 2x f32x2
            ffma2(acc[r], e.x, w01);
            ffma2(acc[r], e.y, w23);
        }
    }

    const float b = Qb[t];
#pragma unroll
    for (int r = 0; r < RB; r++) {
        float v = unpack_sum(acc[r]) + b;
        v = (v >= 0.f) ? v : ALPHA * v;
        g_H[(size_t)(row0 + r) * HH + t] = v;
    }
}

// ---------------------------------------------------------------------------
// K2: wsh[b,n,h] = sum_k H[b,js[k],h]*ws[k] / (sum_k ws + eps)
// One block per n, both batches. 128 threads = 32 col-groups x 4 k-groups.
// float4 gathers, 16 independent LDG.128/thread, smem cross-warp reduce.
// ---------------------------------------------------------------------------
__global__ void __launch_bounds__(128) k2_gather(const float* __restrict__ weights,
                                                 const int* __restrict__ ns) {
    const int n = blockIdx.x;
    const int t = threadIdx.x;
    const int c4 = t & 31;   // column group: h = 4*c4 .. 4*c4+3
    const int kg = t >> 5;   // k-group 0..3

    __shared__ float ws[KK];
    __shared__ int   js[KK];
    __shared__ float wsum_s;
    __shared__ float4 red0[4][32];
    __shared__ float4 red1[4][32];

    if (t < KK) {
        int j = ns[n * KK + t];
        js[t] = j;
        float w = weights[(size_t)n * NN + j];
        ws[t] = w;
#pragma unroll
        for (int off = 16; off; off >>= 1)
            w += __shfl_xor_sync(0xffffffffu, w, off);
        if (t == 0) wsum_s = w;
    }
    __syncthreads();

    const float* H0 = g_H;
    const float* H1 = g_H + (size_t)NN * HH;
    float4 a0 = make_float4(0.f, 0.f, 0.f, 0.f);
    float4 a1 = make_float4(0.f, 0.f, 0.f, 0.f);
#pragma unroll
    for (int k = kg; k < KK; k += 4) {
        const int j = js[k];
        const float w = ws[k];
        const float4 h0 = *(const float4*)&H0[(size_t)j * HH + 4 * c4];
        const float4 h1 = *(const float4*)&H1[(size_t)j * HH + 4 * c4];
        a0.x = fmaf(h0.x, w, a0.x); a0.y = fmaf(h0.y, w, a0.y);
        a0.z = fmaf(h0.z, w, a0.z); a0.w = fmaf(h0.w, w, a0.w);
        a1.x = fmaf(h1.x, w, a1.x); a1.y = fmaf(h1.y, w, a1.y);
        a1.z = fmaf(h1.z, w, a1.z); a1.w = fmaf(h1.w, w, a1.w);
    }
    red0[kg][c4] = a0;
    red1[kg][c4] = a1;
    __syncthreads();

    if (t < 64) {
        const int b = t >> 5;      // 0 or 1
        const int c = t & 31;
        const float4 p0 = b ? red1[0][c] : red0[0][c];
        const float4 p1 = b ? red1[1][c] : red0[1][c];
        const float4 p2 = b ? red1[2][c] : red0[2][c];
        const float4 p3 = b ? red1[3][c] : red0[3][c];
        const float inv = 1.f / (wsum_s + EPS);
        float4 o;
        o.x = (p0.x + p1.x + p2.x + p3.x) * inv;
        o.y = (p0.y + p1.y + p2.y + p3.y) * inv;
        o.z = (p0.z + p1.z + p2.z + p3.z) * inv;
        o.w = (p0.w + p1.w + p2.w + p3.w) * inv;
        *(float4*)&g_wsh[((size_t)b * NN + n) * HH + 4 * c] = o;
    }
}

// ---------------------------------------------------------------------------
// K3: out[row,h] = normalize_h( leaky( [emb_row | wsh_row] @ Ww + Wb ) )
// Block = 16 rows x 128 threads, packed-f32x2 inner loop, fused epilogue.
// ---------------------------------------------------------------------------
__global__ void __launch_bounds__(128) k3_out(const float* __restrict__ emb,
                                              const float* __restrict__ Ww,
                                              const float* __restrict__ Wb,
                                              float* __restrict__ out) {
    const int RB = 16;
    __shared__ float cs[RB][CC + HH];   // 16 KB
    __shared__ float red[RB][4];
    const int row0 = blockIdx.x * RB;
    const int t = threadIdx.x;

    const float4* se = (const float4*)(emb   + (size_t)row0 * CC);
    const float4* sw = (const float4*)(g_wsh + (size_t)row0 * HH);
#pragma unroll
    for (int i = 0; i < (RB * CC / 4) / 128; i++) {
        int idx = t + i * 128;
        int r = idx >> 5;
        int c4 = idx & 31;
        ((float4*)&cs[r][0])[c4]  = se[idx];
        ((float4*)&cs[r][CC])[c4] = sw[idx];
    }
    __syncthreads();

    unsigned long long acc[RB];
#pragma unroll
    for (int r = 0; r < RB; r++) acc[r] = 0ull;

#pragma unroll 4
    for (int f = 0; f < CC + HH; f += 4) {
        const unsigned long long w01 = pack2(Ww[(f + 0) * HH + t], Ww[(f + 1) * HH + t]);
        const unsigned long long w23 = pack2(Ww[(f + 2) * HH + t], Ww[(f + 3) * HH + t]);
#pragma unroll
        for (int r = 0; r < RB; r++) {
            const ulonglong2 e = *(const ulonglong2*)&cs[r][f];  // LDS.128
            ffma2(acc[r], e.x, w01);
            ffma2(acc[r], e.y, w23);
        }
    }

    const float b = Wb[t];
    const int warp = t >> 5, lane = t & 31;
    float vals[RB];
#pragma unroll
    for (int r = 0; r < RB; r++) {
        float v = unpack_sum(acc[r]) + b;
        v = (v >= 0.f) ? v : ALPHA * v;
        vals[r] = v;
        float s = v * v;
#pragma unroll
        for (int off = 16; off; off >>= 1)
            s += __shfl_xor_sync(0xffffffffu, s, off);
        if (lane == 0) red[r][warp] = s;
    }
    __syncthreads();

#pragma unroll
    for (int r = 0; r < RB; r++) {
        float nrm = sqrtf(red[r][0] + red[r][1] + red[r][2] + red[r][3]);
        out[(size_t)(row0 + r) * HH + t] = vals[r] / (nrm + EPS);
    }
}

// ---------------------------------------------------------------------------
extern "C" void kernel_launch(void* const* d_in, const int* in_sizes, int n_in,
                              void* d_out, int out_size) {
    const float* emb     = (const float*)d_in[0];  // (B, N, C)
    const float* weights = (const float*)d_in[1];  // (N, N)
    const int*   ns      = (const int*)  d_in[2];  // (N, K)
    const float* Qw      = (const float*)d_in[3];  // (C, H)
    const float* Qb      = (const float*)d_in[4];  // (H,)
    const float* Ww      = (const float*)d_in[5];  // (C+H, H)
    const float* Wb      = (const float*)d_in[6];  // (H,)
    float* out = (float*)d_out;                    // (B, N, H)

    (void)in_sizes; (void)n_in; (void)out_size;

    k1_qgemm<<<(BB * NN) / 16, 128>>>(emb, Qw, Qb);
    k2_gather<<<NN, 128>>>(weights, ns);
    k3_out<<<(BB * NN) / 16, 128>>>(emb, Ww, Wb, out);
}